// round 1
// baseline (speedup 1.0000x reference)
#include <cuda_runtime.h>
#include <cuda_fp16.h>
#include <mma.h>
#include <cstdint>
#include <cstdio>

using namespace nvcuda;

#define BATCH 4096
#define WID   1024
#define KMAX  (9*1024)

// ---------------- scratch (device globals: allowed) ----------------
__device__ __half g_Ahi[(size_t)BATCH*KMAX];
__device__ __half g_Alo[(size_t)BATCH*KMAX];
__device__ __half g_Whi[(size_t)WID*KMAX];
__device__ __half g_Wlo[(size_t)WID*KMAX];
__device__ float  g_X0[(size_t)BATCH*WID];
__device__ float  g_X1[(size_t)BATCH*WID];

// ---------------- B-spline grid ----------------
__device__ __forceinline__ float gridpt(int j){
    const float h = 2.0f/5.0f;                // matches f32(2.0/GRID_SIZE)
    return (float)(j-3)*h - 1.0f;             // arange(-3, 9)*h - 1
}

// ---------------- expand A = [x | basis(x)] into fp16 hi/lo ----------------
__global__ void expandA_kernel(const float* __restrict__ x, int NIN){
    int idx = blockIdx.x*blockDim.x + threadIdx.x;
    int total = BATCH*NIN;
    if (idx >= total) return;
    int b = idx / NIN;
    int i = idx - b*NIN;
    float xv = x[idx];

    float bas[11];
    #pragma unroll
    for (int c=0;c<11;c++)
        bas[c] = (xv >= gridpt(c) && xv < gridpt(c+1)) ? 1.0f : 0.0f;
    #pragma unroll
    for (int p=1;p<=3;p++){
        #pragma unroll
        for (int c=0;c<=10-p;c++){
            float t1 = (xv - gridpt(c)) / (gridpt(c+p)   - gridpt(c)   + 1e-8f) * bas[c];
            float t2 = (gridpt(c+p+1) - xv) / (gridpt(c+p+1) - gridpt(c+1) + 1e-8f) * bas[c+1];
            bas[c] = t1 + t2;
        }
    }
    int K = 9*NIN;
    size_t rb = (size_t)b*K;
    __half hh = __float2half_rn(xv);
    g_Ahi[rb + i] = hh;
    g_Alo[rb + i] = __float2half_rn(xv - __half2float(hh));
    size_t off = rb + NIN + (size_t)i*8;
    #pragma unroll
    for (int c=0;c<8;c++){
        float v = bas[c];
        __half vh = __float2half_rn(v);
        g_Ahi[off+c] = vh;
        g_Alo[off+c] = __float2half_rn(v - __half2float(vh));
    }
}

// ---------------- expand W = [base_w | round(spline_w*32)/32] ----------------
__global__ void expandW_kernel(const float* __restrict__ bw, const float* __restrict__ sw, int NIN){
    int idx = blockIdx.x*blockDim.x + threadIdx.x;
    int K = 9*NIN;
    int total = WID*K;
    if (idx >= total) return;
    int o = idx / K;
    int k = idx - o*K;
    float w;
    if (k < NIN){
        w = bw[(size_t)o*NIN + k];
    } else {
        w = sw[(size_t)o*NIN*8 + (k - NIN)];
        w = rintf(w * 32.0f) * 0.03125f;      // exact in fp16 -> Wlo == 0 here
    }
    __half wh = __float2half_rn(w);
    g_Whi[idx] = wh;
    g_Wlo[idx] = __float2half_rn(w - __half2float(wh));
}

// ---------------- split-fp16 GEMM: C = Ahi*Whi + Alo*Whi + Ahi*Wlo ----------------
#define BM 128
#define BN 128
#define BK 16
#define SK 24

__device__ __forceinline__ void cpa16(void* sm, const void* gm){
    unsigned sa = (unsigned)__cvta_generic_to_shared(sm);
    asm volatile("cp.async.ca.shared.global [%0], [%1], 16;\n" :: "r"(sa), "l"(gm));
}

__global__ __launch_bounds__(256) void gemm_kernel(float* __restrict__ C, int K, int Kb){
    __shared__ alignas(16) __half sAh[2][BM*SK];
    __shared__ alignas(16) __half sAl[2][BM*SK];
    __shared__ alignas(16) __half sWh[2][BN*SK];
    __shared__ alignas(16) __half sWl[2][BN*SK];

    int tid = threadIdx.x;
    int wid = tid >> 5;
    int wm = wid & 3;        // warp row 0..3  (32 M each)
    int wn = wid >> 2;       // warp col 0..1  (64 N each)
    int bm = blockIdx.y * BM;
    int bn = blockIdx.x * BN;

    int lrow = tid >> 1;
    int lcol = (tid & 1) * 8;

    wmma::fragment<wmma::accumulator,16,16,16,float> acc[2][4];
    #pragma unroll
    for (int i=0;i<2;i++)
        #pragma unroll
        for (int j=0;j<4;j++) wmma::fill_fragment(acc[i][j], 0.0f);

    const int KT = K / BK;

    auto issue = [&](int st, int kt){
        int k0 = kt*BK;
        cpa16(&sAh[st][lrow*SK + lcol], g_Ahi + (size_t)(bm+lrow)*K + k0 + lcol);
        cpa16(&sAl[st][lrow*SK + lcol], g_Alo + (size_t)(bm+lrow)*K + k0 + lcol);
        cpa16(&sWh[st][lrow*SK + lcol], g_Whi + (size_t)(bn+lrow)*K + k0 + lcol);
        if (k0 < Kb)
            cpa16(&sWl[st][lrow*SK + lcol], g_Wlo + (size_t)(bn+lrow)*K + k0 + lcol);
        asm volatile("cp.async.commit_group;\n" ::: "memory");
    };

    issue(0, 0);
    for (int kt=0; kt<KT; kt++){
        int st = kt & 1;
        if (kt+1 < KT) issue(st^1, kt+1);
        else asm volatile("cp.async.commit_group;\n" ::: "memory");
        asm volatile("cp.async.wait_group 1;\n" ::: "memory");
        __syncthreads();

        bool wlo = (kt*BK) < Kb;
        wmma::fragment<wmma::matrix_b,16,16,16,__half,wmma::col_major> fb[4], fbl[4];
        #pragma unroll
        for (int j=0;j<4;j++)
            wmma::load_matrix_sync(fb[j], &sWh[st][(wn*64 + j*16)*SK], SK);
        if (wlo){
            #pragma unroll
            for (int j=0;j<4;j++)
                wmma::load_matrix_sync(fbl[j], &sWl[st][(wn*64 + j*16)*SK], SK);
        }
        #pragma unroll
        for (int i=0;i<2;i++){
            wmma::fragment<wmma::matrix_a,16,16,16,__half,wmma::row_major> fah, fal;
            wmma::load_matrix_sync(fah, &sAh[st][(wm*32 + i*16)*SK], SK);
            wmma::load_matrix_sync(fal, &sAl[st][(wm*32 + i*16)*SK], SK);
            #pragma unroll
            for (int j=0;j<4;j++){
                wmma::mma_sync(acc[i][j], fah, fb[j],  acc[i][j]);
                wmma::mma_sync(acc[i][j], fal, fb[j],  acc[i][j]);
                if (wlo) wmma::mma_sync(acc[i][j], fah, fbl[j], acc[i][j]);
            }
        }
        __syncthreads();
    }
    #pragma unroll
    for (int i=0;i<2;i++)
        #pragma unroll
        for (int j=0;j<4;j++){
            float* cp = C + (size_t)(bm + wm*32 + i*16)*WID + bn + wn*64 + j*16;
            wmma::store_matrix_sync(cp, acc[i][j], WID, wmma::mem_row_major);
        }
}

// ---------------- huxley_rd + trig_unfolding (1 block per row) ----------------
#define FN 1024
#define HT 256

__global__ __launch_bounds__(HT) void huxley_kernel(
    const float* __restrict__ X,
    const float* __restrict__ sgate,
    const float* __restrict__ dk,
    const float* __restrict__ a_p,
    const float* __restrict__ gamma_p,
    const float* __restrict__ tau_p,
    const float* __restrict__ vel_p,
    const float* __restrict__ gcve,
    const float* __restrict__ chir,
    float* __restrict__ out)
{
    __shared__ float2 Z[FN];
    __shared__ float2 TW[FN/2];
    __shared__ float  mg[FN/2 + 1];
    __shared__ float  red[HT];

    const int row = blockIdx.x;
    const int t = threadIdx.x;
    const float PI = 3.14159265358979323846f;

    for (int i=t;i<FN/2;i+=HT){
        float s,c;
        sincosf(-2.0f*PI*(float)i/(float)FN, &s, &c);
        TW[i] = make_float2(c, s);
    }
    for (int i=t;i<FN;i+=HT){
        unsigned r = __brev((unsigned)i) >> 22;
        Z[r] = make_float2(X[(size_t)row*FN + i], 0.0f);
    }
    __syncthreads();

    // forward FFT (DIT, bit-reversed input, e^{-i...})
    for (int s=0;s<10;s++){
        int half = 1<<s;
        for (int j=t;j<FN/2;j+=HT){
            int pos = j & (half-1);
            int i0 = ((j >> s) << (s+1)) + pos;
            int i1 = i0 + half;
            float2 w = TW[pos << (9-s)];
            float2 a = Z[i0], b = Z[i1];
            float2 wb = make_float2(w.x*b.x - w.y*b.y, w.x*b.y + w.y*b.x);
            Z[i0] = make_float2(a.x+wb.x, a.y+wb.y);
            Z[i1] = make_float2(a.x-wb.x, a.y-wb.y);
        }
        __syncthreads();
    }

    // build combined inverse spectrum Z = E + iS, and |nef| magnitudes
    float v = vel_p[0];
    for (int k=t;k<=FN/2;k+=HT){
        float2 F = Z[k];
        float g = 1.0f/(1.0f + expf(-sgate[k]));
        float og = 1.0f - g;
        float ps, pc;
        sincosf(-2.0f*PI*(float)k*v/(float)FN, &ps, &pc);
        float2 nef = make_float2(F.x*og, F.y*og);
        float2 S = make_float2(nef.x*pc - nef.y*ps, nef.x*ps + nef.y*pc);
        float2 E = make_float2(F.x*g, F.y*g);
        if (k==0 || k==FN/2){
            mg[k] = fabsf(S.x);                    // C2R convention: Re() at bins 0, N/2
            Z[k] = make_float2(E.x, S.x);
        } else {
            mg[k] = sqrtf(nef.x*nef.x + nef.y*nef.y);   // |nef*phase| = |nef|
            Z[k]    = make_float2(E.x - S.y, E.y + S.x);
            Z[FN-k] = make_float2(E.x + S.y, S.x - E.y);
        }
    }
    __syncthreads();

    // stats over mg[0..512]: mean, min, var(ddof=1)
    float ls=0.0f, lmin=3.4e38f;
    for (int k=t;k<=FN/2;k+=HT){ ls += mg[k]; lmin = fminf(lmin, mg[k]); }
    red[t]=ls; __syncthreads();
    for (int o=HT/2;o>0;o>>=1){ if(t<o) red[t]+=red[t+o]; __syncthreads(); }
    float mean = red[0] / 513.0f; __syncthreads();
    red[t]=lmin; __syncthreads();
    for (int o=HT/2;o>0;o>>=1){ if(t<o) red[t]=fminf(red[t],red[t+o]); __syncthreads(); }
    float lam_min = red[0]; __syncthreads();
    float lv=0.0f;
    for (int k=t;k<=FN/2;k+=HT){ float d = mg[k]-mean; lv += d*d; }
    red[t]=lv; __syncthreads();
    for (int o=HT/2;o>0;o>>=1){ if(t<o) red[t]+=red[t+o]; __syncthreads(); }
    float var = red[0] / 512.0f; __syncthreads();

    // inverse FFT in place: bit-reverse then DIT with conj twiddles
    for (int i=t;i<FN;i+=HT){
        unsigned r = __brev((unsigned)i) >> 22;
        if (i < (int)r){ float2 tmp = Z[i]; Z[i]=Z[r]; Z[r]=tmp; }
    }
    __syncthreads();
    for (int s=0;s<10;s++){
        int half = 1<<s;
        for (int j=t;j<FN/2;j+=HT){
            int pos = j & (half-1);
            int i0 = ((j >> s) << (s+1)) + pos;
            int i1 = i0 + half;
            float2 w = TW[pos << (9-s)];
            w.y = -w.y;
            float2 a = Z[i0], b = Z[i1];
            float2 wb = make_float2(w.x*b.x - w.y*b.y, w.x*b.y + w.y*b.x);
            Z[i0] = make_float2(a.x+wb.x, a.y+wb.y);
            Z[i1] = make_float2(a.x-wb.x, a.y-wb.y);
        }
        __syncthreads();
    }
    // now: u_erg[n] = Z[n].x/N ; u_ne_shift[n] = Z[n].y/N

    const float scale = 1.0f/(float)FN;
    float lt = 0.0f;
    for (int n=t;n<FN;n+=HT){ float hh = Z[n].y*scale; lt += hh*hh; }
    red[t]=lt; __syncthreads();
    for (int o=HT/2;o>0;o>>=1){ if(t<o) red[t]+=red[t+o]; __syncthreads(); }
    float tr_c = red[0]; __syncthreads();

    float tau = tau_p[0], gam = gamma_p[0], a = a_p[0];
    float k0 = dk[0], k1 = dk[1], k2 = dk[2];
    float gp = gcve[row];
    float ach = fabsf(chir[row]);

    float det = var + 1e-6f;
    float sq = sqrtf(det);
    float denom = 2.0f*(sq*sq*sq) + 1e-8f;
    float cos3 = (3.0f*gp - tr_c/tau) / denom;
    cos3 = fminf(0.999f, fmaxf(-0.999f, cos3));
    float phi = acosf(cos3) / 3.0f;
    float amp = 2.0f*sqrtf(lam_min/3.0f + 1e-8f);
    float c0 = amp * cosf(phi);
    float c1 = amp * cosf(phi + 2.0f*PI/3.0f) * expf(-ach);
    float c2 = amp * cosf(phi + 4.0f*PI/3.0f) * expf(-2.0f*ach);
    float e0=fabsf(c0), e1=fabsf(c1), e2=fabsf(c2);
    float cb = c0; float eb = e0;
    if (e1 > eb){ cb=c1; eb=e1; }
    if (e2 > eb){ cb=c2; }

    for (int n=t;n<FN;n+=HT){
        float e  = Z[n].x*scale;
        float em = (n>0)      ? Z[n-1].x*scale : 0.0f;
        float ep = (n<FN-1)   ? Z[n+1].x*scale : 0.0f;
        float reac = e*(e-a)*(1.0f-e);
        float dif  = k0*em + k1*e + k2*ep;
        float enx  = e + 0.1f*(reac + gam*dif);
        float hh   = Z[n].y*scale;
        float s    = enx + cb*hh;
        float sg   = 1.0f/(1.0f+expf(-s));
        out[(size_t)row*FN + n] = sg*s;
    }
}

// ---------------- launcher ----------------
extern "C" void kernel_launch(void* const* d_in, const int* in_sizes, int n_in,
                              void* d_out, int out_size) {
    const float* c   = (const float*)d_in[0];
    const float* bw0 = (const float*)d_in[1];
    const float* sw0 = (const float*)d_in[2];
    const float* bw1 = (const float*)d_in[3];
    const float* sw1 = (const float*)d_in[4];
    const float* bw2 = (const float*)d_in[5];
    const float* sw2 = (const float*)d_in[6];
    const float* sg  = (const float*)d_in[7];
    const float* dk  = (const float*)d_in[8];
    const float* ap  = (const float*)d_in[9];
    const float* gm  = (const float*)d_in[10];
    const float* td  = (const float*)d_in[11];
    const float* sv  = (const float*)d_in[12];
    const float* gp  = (const float*)d_in[13];
    const float* ch  = (const float*)d_in[14];

    float *X0, *X1;
    cudaGetSymbolAddress((void**)&X0, g_X0);
    cudaGetSymbolAddress((void**)&X1, g_X1);

    dim3 gblk(WID/BN, BATCH/BM);   // (8, 32)

    // layer 1: NIN=512, K=4608
    expandW_kernel<<<(WID*9*512 + 255)/256, 256>>>(bw0, sw0, 512);
    expandA_kernel<<<(BATCH*512 + 255)/256, 256>>>(c, 512);
    gemm_kernel<<<gblk, 256>>>(X0, 9*512, 512);

    // layer 2: NIN=1024, K=9216
    expandW_kernel<<<(WID*9*1024 + 255)/256, 256>>>(bw1, sw1, 1024);
    expandA_kernel<<<(BATCH*1024 + 255)/256, 256>>>(X0, 1024);
    gemm_kernel<<<gblk, 256>>>(X1, 9*1024, 1024);

    // layer 3
    expandW_kernel<<<(WID*9*1024 + 255)/256, 256>>>(bw2, sw2, 1024);
    expandA_kernel<<<(BATCH*1024 + 255)/256, 256>>>(X1, 1024);
    gemm_kernel<<<gblk, 256>>>(X0, 9*1024, 1024);

    // spectral reaction-diffusion epilogue
    huxley_kernel<<<BATCH, HT>>>(X0, sg, dk, ap, gm, td, sv, gp, ch, (float*)d_out);
}

// round 3
// speedup vs baseline: 1.0626x; 1.0626x over previous
#include <cuda_runtime.h>
#include <cuda_fp16.h>
#include <cstdint>

#define BATCH 4096
#define WID   1024
#define KMAX  (9*1024)

// ---------------- scratch (device globals: allowed) ----------------
__device__ __half g_Ahi[(size_t)BATCH*KMAX];
__device__ __half g_Alo[(size_t)BATCH*KMAX];
__device__ __half g_Whi[(size_t)WID*KMAX];
__device__ __half g_Wlo[(size_t)WID*1024];     // compact: only base_w section (Kb cols)
__device__ float  g_X0[(size_t)BATCH*WID];
__device__ float  g_X1[(size_t)BATCH*WID];

// ---------------- helpers ----------------
__device__ __forceinline__ uint32_t smem_u32(const void* p){
    return (uint32_t)__cvta_generic_to_shared(p);
}
__device__ __forceinline__ void cpa16(uint32_t dst, const void* src){
    asm volatile("cp.async.ca.shared.global [%0], [%1], 16;\n" :: "r"(dst), "l"(src));
}
__device__ __forceinline__ void ldsm4(uint32_t* r, uint32_t addr){
    asm volatile("ldmatrix.sync.aligned.m8n8.x4.shared.b16 {%0,%1,%2,%3}, [%4];\n"
        : "=r"(r[0]), "=r"(r[1]), "=r"(r[2]), "=r"(r[3]) : "r"(addr));
}
#define MMA16816(d, a, b0, b1)                                                        \
    asm volatile("mma.sync.aligned.m16n8k16.row.col.f32.f16.f16.f32 "                 \
        "{%0,%1,%2,%3},{%4,%5,%6,%7},{%8,%9},{%0,%1,%2,%3};\n"                        \
        : "+f"((d)[0]), "+f"((d)[1]), "+f"((d)[2]), "+f"((d)[3])                      \
        : "r"((a)[0]), "r"((a)[1]), "r"((a)[2]), "r"((a)[3]), "r"(b0), "r"(b1))

// swizzled smem address: 128B rows, 16B chunk index XOR (row % 8)
__device__ __forceinline__ uint32_t swaddr(uint32_t base, int r, int k /*half idx*/){
    return base + (r << 7) + ((((k >> 3) ^ r) & 7) << 4) + ((k & 7) << 1);
}

// ---------------- HMMA split-fp16 GEMM ----------------
// C[128x128 per CTA] = Ahi*Whi^T + Alo*Whi^T + Ahi*Wlo^T  (fp32 accum)
#define BKH 64
#define STAGE_BYTES 65536
#define SMEM_BYTES  (3*STAGE_BYTES)

__device__ __forceinline__ void load_tile(uint32_t dstBase, const __half* g, int strideHalves){
    int t = threadIdx.x;
    #pragma unroll
    for (int i = 0; i < 4; i++){
        int q = t + i*256;
        int r = q >> 3, c = q & 7;
        uint32_t d = dstBase + (r << 7) + (((c ^ r) & 7) << 4);
        const char* s = (const char*)(g + (size_t)r * strideHalves) + (c << 4);
        cpa16(d, s);
    }
}

__global__ void __launch_bounds__(256, 1) hmma_gemm(
    const __half* __restrict__ Ahi, const __half* __restrict__ Alo,
    const __half* __restrict__ Whi, const __half* __restrict__ Wlo,
    float* __restrict__ C, int K, int Kb)
{
    extern __shared__ __align__(128) char smem[];
    uint32_t sb = smem_u32(smem);
    const int tid = threadIdx.x, wid = tid >> 5, lane = tid & 31;
    const int wm = wid & 3, wn = wid >> 2;
    const int bm = blockIdx.y * 128, bn = blockIdx.x * 128;
    const int NC = K / BKH;

    const __half* gAhi = Ahi + (size_t)bm * K;
    const __half* gAlo = Alo + (size_t)bm * K;
    const __half* gWhi = Whi + (size_t)bn * K;
    const __half* gWlo = Wlo + (size_t)bn * Kb;

    auto load_chunk = [&](int c){
        int st = c % 3;
        uint32_t base = sb + st * STAGE_BYTES;
        int k0 = c * BKH;
        load_tile(base,         gAhi + k0, K);
        load_tile(base + 16384, gAlo + k0, K);
        load_tile(base + 32768, gWhi + k0, K);
        if (k0 < Kb) load_tile(base + 49152, gWlo + k0, Kb);
    };

    float acc[2][8][4];
    #pragma unroll
    for (int i = 0; i < 2; i++)
        #pragma unroll
        for (int j = 0; j < 8; j++)
            #pragma unroll
            for (int q = 0; q < 4; q++) acc[i][j][q] = 0.0f;

    load_chunk(0); asm volatile("cp.async.commit_group;\n" ::: "memory");
    load_chunk(1); asm volatile("cp.async.commit_group;\n" ::: "memory");
    load_chunk(2); asm volatile("cp.async.commit_group;\n" ::: "memory");

    for (int c = 0; c < NC; c++){
        asm volatile("cp.async.wait_group 2;\n" ::: "memory");
        __syncthreads();
        int st = c % 3;
        uint32_t sAh = sb + st * STAGE_BYTES;
        uint32_t sAl = sAh + 16384;
        uint32_t sWh = sAh + 32768;
        uint32_t sWl = sAh + 49152;
        bool lo = (c * BKH) < Kb;

        #pragma unroll
        for (int ks = 0; ks < 4; ks++){
            int k0 = ks * 16;
            int ka = k0 + ((lane >> 4) << 3);           // A frag k offset
            int kb = k0 + (((lane >> 3) & 1) << 3);     // B frag k offset
            uint32_t ah[2][4], al[2][4], bh[4][4], bl[4][4];
            #pragma unroll
            for (int i = 0; i < 2; i++){
                int r = wm*32 + i*16 + (lane & 15);
                ldsm4(ah[i], swaddr(sAh, r, ka));
                ldsm4(al[i], swaddr(sAl, r, ka));
            }
            #pragma unroll
            for (int p = 0; p < 4; p++){
                int n = wn*64 + p*16 + ((lane >> 4) << 3) + (lane & 7);
                ldsm4(bh[p], swaddr(sWh, n, kb));
            }
            if (lo){
                #pragma unroll
                for (int p = 0; p < 4; p++){
                    int n = wn*64 + p*16 + ((lane >> 4) << 3) + (lane & 7);
                    ldsm4(bl[p], swaddr(sWl, n, kb));
                }
            }
            #pragma unroll
            for (int i = 0; i < 2; i++){
                #pragma unroll
                for (int p = 0; p < 4; p++){
                    MMA16816(acc[i][2*p+0], ah[i], bh[p][0], bh[p][1]);
                    MMA16816(acc[i][2*p+1], ah[i], bh[p][2], bh[p][3]);
                    MMA16816(acc[i][2*p+0], al[i], bh[p][0], bh[p][1]);
                    MMA16816(acc[i][2*p+1], al[i], bh[p][2], bh[p][3]);
                }
            }
            if (lo){
                #pragma unroll
                for (int i = 0; i < 2; i++){
                    #pragma unroll
                    for (int p = 0; p < 4; p++){
                        MMA16816(acc[i][2*p+0], ah[i], bl[p][0], bl[p][1]);
                        MMA16816(acc[i][2*p+1], ah[i], bl[p][2], bl[p][3]);
                    }
                }
            }
        }
        __syncthreads();
        if (c + 3 < NC) load_chunk(c + 3);
        asm volatile("cp.async.commit_group;\n" ::: "memory");
    }

    // epilogue: registers -> gmem
    #pragma unroll
    for (int i = 0; i < 2; i++){
        int row = bm + wm*32 + i*16 + (lane >> 2);
        #pragma unroll
        for (int j = 0; j < 8; j++){
            int col = bn + wn*64 + j*8 + ((lane & 3) << 1);
            float* p = C + (size_t)row * WID + col;
            *reinterpret_cast<float2*>(p)             = make_float2(acc[i][j][0], acc[i][j][1]);
            *reinterpret_cast<float2*>(p + 8*WID)     = make_float2(acc[i][j][2], acc[i][j][3]);
        }
    }
}

// ---------------- B-spline grid ----------------
__device__ __forceinline__ float gridpt(int j){
    const float h = 2.0f/5.0f;
    return (float)(j-3)*h - 1.0f;
}

// ---------------- expand A = [x | basis(x)] into fp16 hi/lo ----------------
__global__ void expandA_kernel(const float* __restrict__ x, int NIN){
    int idx = blockIdx.x*blockDim.x + threadIdx.x;
    int total = BATCH*NIN;
    if (idx >= total) return;
    int b = idx / NIN;
    int i = idx - b*NIN;
    float xv = x[idx];

    float bas[11];
    #pragma unroll
    for (int c=0;c<11;c++)
        bas[c] = (xv >= gridpt(c) && xv < gridpt(c+1)) ? 1.0f : 0.0f;
    #pragma unroll
    for (int p=1;p<=3;p++){
        #pragma unroll
        for (int c=0;c<=10-p;c++){
            float t1 = (xv - gridpt(c)) / (gridpt(c+p)   - gridpt(c)   + 1e-8f) * bas[c];
            float t2 = (gridpt(c+p+1) - xv) / (gridpt(c+p+1) - gridpt(c+1) + 1e-8f) * bas[c+1];
            bas[c] = t1 + t2;
        }
    }
    int K = 9*NIN;
    size_t rb = (size_t)b*K;
    __half hh = __float2half_rn(xv);
    g_Ahi[rb + i] = hh;
    g_Alo[rb + i] = __float2half_rn(xv - __half2float(hh));
    size_t off = rb + NIN + (size_t)i*8;
    #pragma unroll
    for (int c=0;c<8;c++){
        float v = bas[c];
        __half vh = __float2half_rn(v);
        g_Ahi[off+c] = vh;
        g_Alo[off+c] = __float2half_rn(v - __half2float(vh));
    }
}

// ---------------- expand W = [base_w | round(spline_w*32)/32] ----------------
__global__ void expandW_kernel(const float* __restrict__ bw, const float* __restrict__ sw, int NIN){
    int idx = blockIdx.x*blockDim.x + threadIdx.x;
    int K = 9*NIN;
    int total = WID*K;
    if (idx >= total) return;
    int o = idx / K;
    int k = idx - o*K;
    if (k < NIN){
        float w = bw[(size_t)o*NIN + k];
        __half wh = __float2half_rn(w);
        g_Whi[idx] = wh;
        g_Wlo[(size_t)o*NIN + k] = __float2half_rn(w - __half2float(wh));
    } else {
        float w = sw[(size_t)o*NIN*8 + (k - NIN)];
        w = rintf(w * 32.0f) * 0.03125f;      // exact in fp16 -> no lo part
        g_Whi[idx] = __float2half_rn(w);
    }
}

// ---------------- huxley_rd + trig_unfolding (1 block per row) ----------------
#define FN 1024
#define HT 256

__global__ void __launch_bounds__(HT) huxley_kernel(
    const float* __restrict__ X,
    const float* __restrict__ sgate,
    const float* __restrict__ dk,
    const float* __restrict__ a_p,
    const float* __restrict__ gamma_p,
    const float* __restrict__ tau_p,
    const float* __restrict__ vel_p,
    const float* __restrict__ gcve,
    const float* __restrict__ chir,
    float* __restrict__ out)
{
    __shared__ float2 Z[FN];
    __shared__ float2 TW[FN/2];
    __shared__ float  mg[FN/2 + 1];
    __shared__ float  red[HT];

    const int row = blockIdx.x;
    const int t = threadIdx.x;
    const float PI = 3.14159265358979323846f;

    for (int i=t;i<FN/2;i+=HT){
        float s,c;
        sincosf(-2.0f*PI*(float)i/(float)FN, &s, &c);
        TW[i] = make_float2(c, s);
    }
    for (int i=t;i<FN;i+=HT){
        unsigned r = __brev((unsigned)i) >> 22;
        Z[r] = make_float2(X[(size_t)row*FN + i], 0.0f);
    }
    __syncthreads();

    for (int s=0;s<10;s++){
        int half = 1<<s;
        for (int j=t;j<FN/2;j+=HT){
            int pos = j & (half-1);
            int i0 = ((j >> s) << (s+1)) + pos;
            int i1 = i0 + half;
            float2 w = TW[pos << (9-s)];
            float2 a = Z[i0], b = Z[i1];
            float2 wb = make_float2(w.x*b.x - w.y*b.y, w.x*b.y + w.y*b.x);
            Z[i0] = make_float2(a.x+wb.x, a.y+wb.y);
            Z[i1] = make_float2(a.x-wb.x, a.y-wb.y);
        }
        __syncthreads();
    }

    float v = vel_p[0];
    for (int k=t;k<=FN/2;k+=HT){
        float2 F = Z[k];
        float g = 1.0f/(1.0f + expf(-sgate[k]));
        float og = 1.0f - g;
        float ps, pc;
        sincosf(-2.0f*PI*(float)k*v/(float)FN, &ps, &pc);
        float2 nef = make_float2(F.x*og, F.y*og);
        float2 S = make_float2(nef.x*pc - nef.y*ps, nef.x*ps + nef.y*pc);
        float2 E = make_float2(F.x*g, F.y*g);
        if (k==0 || k==FN/2){
            mg[k] = fabsf(S.x);
            Z[k] = make_float2(E.x, S.x);
        } else {
            mg[k] = sqrtf(nef.x*nef.x + nef.y*nef.y);
            Z[k]    = make_float2(E.x - S.y, E.y + S.x);
            Z[FN-k] = make_float2(E.x + S.y, S.x - E.y);
        }
    }
    __syncthreads();

    float ls=0.0f, lmin=3.4e38f;
    for (int k=t;k<=FN/2;k+=HT){ ls += mg[k]; lmin = fminf(lmin, mg[k]); }
    red[t]=ls; __syncthreads();
    for (int o=HT/2;o>0;o>>=1){ if(t<o) red[t]+=red[t+o]; __syncthreads(); }
    float mean = red[0] / 513.0f; __syncthreads();
    red[t]=lmin; __syncthreads();
    for (int o=HT/2;o>0;o>>=1){ if(t<o) red[t]=fminf(red[t],red[t+o]); __syncthreads(); }
    float lam_min = red[0]; __syncthreads();
    float lv=0.0f;
    for (int k=t;k<=FN/2;k+=HT){ float d = mg[k]-mean; lv += d*d; }
    red[t]=lv; __syncthreads();
    for (int o=HT/2;o>0;o>>=1){ if(t<o) red[t]+=red[t+o]; __syncthreads(); }
    float var = red[0] / 512.0f; __syncthreads();

    for (int i=t;i<FN;i+=HT){
        unsigned r = __brev((unsigned)i) >> 22;
        if (i < (int)r){ float2 tmp = Z[i]; Z[i]=Z[r]; Z[r]=tmp; }
    }
    __syncthreads();
    for (int s=0;s<10;s++){
        int half = 1<<s;
        for (int j=t;j<FN/2;j+=HT){
            int pos = j & (half-1);
            int i0 = ((j >> s) << (s+1)) + pos;
            int i1 = i0 + half;
            float2 w = TW[pos << (9-s)];
            w.y = -w.y;
            float2 a = Z[i0], b = Z[i1];
            float2 wb = make_float2(w.x*b.x - w.y*b.y, w.x*b.y + w.y*b.x);
            Z[i0] = make_float2(a.x+wb.x, a.y+wb.y);
            Z[i1] = make_float2(a.x-wb.x, a.y-wb.y);
        }
        __syncthreads();
    }

    const float scale = 1.0f/(float)FN;
    float lt = 0.0f;
    for (int n=t;n<FN;n+=HT){ float hh = Z[n].y*scale; lt += hh*hh; }
    red[t]=lt; __syncthreads();
    for (int o=HT/2;o>0;o>>=1){ if(t<o) red[t]+=red[t+o]; __syncthreads(); }
    float tr_c = red[0]; __syncthreads();

    float tau = tau_p[0], gam = gamma_p[0], a = a_p[0];
    float k0 = dk[0], k1 = dk[1], k2 = dk[2];
    float gp = gcve[row];
    float ach = fabsf(chir[row]);

    float det = var + 1e-6f;
    float sq = sqrtf(det);
    float denom = 2.0f*(sq*sq*sq) + 1e-8f;
    float cos3 = (3.0f*gp - tr_c/tau) / denom;
    cos3 = fminf(0.999f, fmaxf(-0.999f, cos3));
    float phi = acosf(cos3) / 3.0f;
    float amp = 2.0f*sqrtf(lam_min/3.0f + 1e-8f);
    float c0 = amp * cosf(phi);
    float c1 = amp * cosf(phi + 2.0f*PI/3.0f) * expf(-ach);
    float c2 = amp * cosf(phi + 4.0f*PI/3.0f) * expf(-2.0f*ach);
    float e0=fabsf(c0), e1=fabsf(c1), e2=fabsf(c2);
    float cb = c0; float eb = e0;
    if (e1 > eb){ cb=c1; eb=e1; }
    if (e2 > eb){ cb=c2; }

    for (int n=t;n<FN;n+=HT){
        float e  = Z[n].x*scale;
        float em = (n>0)      ? Z[n-1].x*scale : 0.0f;
        float ep = (n<FN-1)   ? Z[n+1].x*scale : 0.0f;
        float reac = e*(e-a)*(1.0f-e);
        float dif  = k0*em + k1*e + k2*ep;
        float enx  = e + 0.1f*(reac + gam*dif);
        float hh   = Z[n].y*scale;
        float s    = enx + cb*hh;
        float sg   = 1.0f/(1.0f+expf(-s));
        out[(size_t)row*FN + n] = sg*s;
    }
}

// ---------------- launcher ----------------
extern "C" void kernel_launch(void* const* d_in, const int* in_sizes, int n_in,
                              void* d_out, int out_size) {
    const float* c   = (const float*)d_in[0];
    const float* bw0 = (const float*)d_in[1];
    const float* sw0 = (const float*)d_in[2];
    const float* bw1 = (const float*)d_in[3];
    const float* sw1 = (const float*)d_in[4];
    const float* bw2 = (const float*)d_in[5];
    const float* sw2 = (const float*)d_in[6];
    const float* sg  = (const float*)d_in[7];
    const float* dk  = (const float*)d_in[8];
    const float* ap  = (const float*)d_in[9];
    const float* gm  = (const float*)d_in[10];
    const float* td  = (const float*)d_in[11];
    const float* sv  = (const float*)d_in[12];
    const float* gp  = (const float*)d_in[13];
    const float* ch  = (const float*)d_in[14];

    void *pAhi, *pAlo, *pWhi, *pWlo;
    float *X0, *X1;
    cudaGetSymbolAddress(&pAhi, g_Ahi);
    cudaGetSymbolAddress(&pAlo, g_Alo);
    cudaGetSymbolAddress(&pWhi, g_Whi);
    cudaGetSymbolAddress(&pWlo, g_Wlo);
    cudaGetSymbolAddress((void**)&X0, g_X0);
    cudaGetSymbolAddress((void**)&X1, g_X1);

    cudaFuncSetAttribute(hmma_gemm, cudaFuncAttributeMaxDynamicSharedMemorySize, SMEM_BYTES);

    dim3 gblk(WID/128, BATCH/128);   // (8, 32)

    struct LayerCfg { const float* bw; const float* sw; const float* in; float* out; int nin; };
    LayerCfg L[3] = {
        { bw0, sw0, c,  X0, 512  },
        { bw1, sw1, X0, X1, 1024 },
        { bw2, sw2, X1, X0, 1024 },
    };

    for (int l = 0; l < 3; l++) {
        int NIN = L[l].nin;
        int K   = 9 * NIN;
        int Kb  = NIN;

        expandW_kernel<<<(WID*K + 255)/256, 256>>>(L[l].bw, L[l].sw, NIN);
        expandA_kernel<<<(BATCH*NIN + 255)/256, 256>>>(L[l].in, NIN);

        hmma_gemm<<<gblk, 256, SMEM_BYTES>>>(
            (const __half*)pAhi, (const __half*)pAlo,
            (const __half*)pWhi, (const __half*)pWlo,
            L[l].out, K, Kb);
    }

    huxley_kernel<<<BATCH, HT>>>(X0, sg, dk, ap, gm, td, sv, gp, ch, (float*)d_out);
}

// round 4
// speedup vs baseline: 1.1640x; 1.0954x over previous
#include <cuda_runtime.h>
#include <cuda_fp16.h>
#include <cstdint>

#define BATCH 4096
#define WID   1024
#define KMAX  (9*1024)

// ---------------- scratch (device globals: allowed) ----------------
__device__ __half g_Ahi[(size_t)BATCH*KMAX];
__device__ __half g_Alo[(size_t)BATCH*KMAX];
__device__ __half g_Whi[(size_t)WID*KMAX];
__device__ __half g_Wlo[(size_t)WID*1024];     // compact: only base_w section (Kb cols)
__device__ float  g_X0[(size_t)BATCH*WID];
__device__ float  g_X1[(size_t)BATCH*WID];

// ---------------- helpers ----------------
__device__ __forceinline__ uint32_t smem_u32(const void* p){
    return (uint32_t)__cvta_generic_to_shared(p);
}
__device__ __forceinline__ void cpa16(uint32_t dst, const void* src){
    asm volatile("cp.async.ca.shared.global [%0], [%1], 16;\n" :: "r"(dst), "l"(src));
}
__device__ __forceinline__ void ldsm4(uint32_t* r, uint32_t addr){
    asm volatile("ldmatrix.sync.aligned.m8n8.x4.shared.b16 {%0,%1,%2,%3}, [%4];\n"
        : "=r"(r[0]), "=r"(r[1]), "=r"(r[2]), "=r"(r[3]) : "r"(addr));
}
#define MMA16816(d, a, b0, b1)                                                        \
    asm volatile("mma.sync.aligned.m16n8k16.row.col.f32.f16.f16.f32 "                 \
        "{%0,%1,%2,%3},{%4,%5,%6,%7},{%8,%9},{%0,%1,%2,%3};\n"                        \
        : "+f"((d)[0]), "+f"((d)[1]), "+f"((d)[2]), "+f"((d)[3])                      \
        : "r"((a)[0]), "r"((a)[1]), "r"((a)[2]), "r"((a)[3]), "r"(b0), "r"(b1))

// swizzled smem address: 128B rows, 16B chunk index XOR (row % 8)
__device__ __forceinline__ uint32_t swaddr(uint32_t base, int r, int k /*half idx*/){
    return base + (r << 7) + ((((k >> 3) ^ r) & 7) << 4) + ((k & 7) << 1);
}

// ---------------- HMMA split-fp16 GEMM ----------------
// C[128x128 per CTA] = Ahi*Whi^T + Alo*Whi^T + Ahi*Wlo^T  (fp32 accum)
#define BKH 64
#define STAGE_BYTES 65536
#define SMEM_BYTES  (3*STAGE_BYTES)

__device__ __forceinline__ void load_tile(uint32_t dstBase, const __half* g, int strideHalves){
    int t = threadIdx.x;
    #pragma unroll
    for (int i = 0; i < 4; i++){
        int q = t + i*256;
        int r = q >> 3, c = q & 7;
        uint32_t d = dstBase + (r << 7) + (((c ^ r) & 7) << 4);
        const char* s = (const char*)(g + (size_t)r * strideHalves) + (c << 4);
        cpa16(d, s);
    }
}

__global__ void __launch_bounds__(256, 1) hmma_gemm(
    const __half* __restrict__ Ahi, const __half* __restrict__ Alo,
    const __half* __restrict__ Whi, const __half* __restrict__ Wlo,
    float* __restrict__ C, int K, int Kb)
{
    extern __shared__ __align__(128) char smem[];
    uint32_t sb = smem_u32(smem);
    const int tid = threadIdx.x, wid = tid >> 5, lane = tid & 31;
    const int wm = wid & 3, wn = wid >> 2;
    const int bm = blockIdx.y * 128, bn = blockIdx.x * 128;
    const int NC = K / BKH;

    const __half* gAhi = Ahi + (size_t)bm * K;
    const __half* gAlo = Alo + (size_t)bm * K;
    const __half* gWhi = Whi + (size_t)bn * K;
    const __half* gWlo = Wlo + (size_t)bn * Kb;

    auto load_chunk = [&](int c){
        int st = c % 3;
        uint32_t base = sb + st * STAGE_BYTES;
        int k0 = c * BKH;
        load_tile(base,         gAhi + k0, K);
        load_tile(base + 16384, gAlo + k0, K);
        load_tile(base + 32768, gWhi + k0, K);
        if (k0 < Kb) load_tile(base + 49152, gWlo + k0, Kb);
    };

    float acc[2][8][4];
    #pragma unroll
    for (int i = 0; i < 2; i++)
        #pragma unroll
        for (int j = 0; j < 8; j++)
            #pragma unroll
            for (int q = 0; q < 4; q++) acc[i][j][q] = 0.0f;

    load_chunk(0); asm volatile("cp.async.commit_group;\n" ::: "memory");
    load_chunk(1); asm volatile("cp.async.commit_group;\n" ::: "memory");
    load_chunk(2); asm volatile("cp.async.commit_group;\n" ::: "memory");

    for (int c = 0; c < NC; c++){
        asm volatile("cp.async.wait_group 2;\n" ::: "memory");
        __syncthreads();
        int st = c % 3;
        uint32_t sAh = sb + st * STAGE_BYTES;
        uint32_t sAl = sAh + 16384;
        uint32_t sWh = sAh + 32768;
        uint32_t sWl = sAh + 49152;
        bool lo = (c * BKH) < Kb;

        #pragma unroll
        for (int ks = 0; ks < 4; ks++){
            int k0 = ks * 16;
            int ka = k0 + ((lane >> 4) << 3);           // A frag k offset
            int kb = k0 + (((lane >> 3) & 1) << 3);     // B frag k offset
            uint32_t ah[2][4], al[2][4], bh[4][4], bl[4][4];
            #pragma unroll
            for (int i = 0; i < 2; i++){
                int r = wm*32 + i*16 + (lane & 15);
                ldsm4(ah[i], swaddr(sAh, r, ka));
                ldsm4(al[i], swaddr(sAl, r, ka));
            }
            #pragma unroll
            for (int p = 0; p < 4; p++){
                int n = wn*64 + p*16 + ((lane >> 4) << 3) + (lane & 7);
                ldsm4(bh[p], swaddr(sWh, n, kb));
            }
            if (lo){
                #pragma unroll
                for (int p = 0; p < 4; p++){
                    int n = wn*64 + p*16 + ((lane >> 4) << 3) + (lane & 7);
                    ldsm4(bl[p], swaddr(sWl, n, kb));
                }
            }
            // ---- pass 1: Ahi * Whi (16 independent MMAs, no same-acc reuse) ----
            #pragma unroll
            for (int p = 0; p < 4; p++){
                #pragma unroll
                for (int i = 0; i < 2; i++){
                    MMA16816(acc[i][2*p+0], ah[i], bh[p][0], bh[p][1]);
                    MMA16816(acc[i][2*p+1], ah[i], bh[p][2], bh[p][3]);
                }
            }
            // ---- pass 2: Alo * Whi (same-acc reuse distance = 16 MMAs) ----
            #pragma unroll
            for (int p = 0; p < 4; p++){
                #pragma unroll
                for (int i = 0; i < 2; i++){
                    MMA16816(acc[i][2*p+0], al[i], bh[p][0], bh[p][1]);
                    MMA16816(acc[i][2*p+1], al[i], bh[p][2], bh[p][3]);
                }
            }
            // ---- pass 3: Ahi * Wlo (base_w K-range only) ----
            if (lo){
                #pragma unroll
                for (int p = 0; p < 4; p++){
                    #pragma unroll
                    for (int i = 0; i < 2; i++){
                        MMA16816(acc[i][2*p+0], ah[i], bl[p][0], bl[p][1]);
                        MMA16816(acc[i][2*p+1], ah[i], bl[p][2], bl[p][3]);
                    }
                }
            }
        }
        __syncthreads();
        if (c + 3 < NC) load_chunk(c + 3);
        asm volatile("cp.async.commit_group;\n" ::: "memory");
    }

    // epilogue: registers -> gmem
    #pragma unroll
    for (int i = 0; i < 2; i++){
        int row = bm + wm*32 + i*16 + (lane >> 2);
        #pragma unroll
        for (int j = 0; j < 8; j++){
            int col = bn + wn*64 + j*8 + ((lane & 3) << 1);
            float* p = C + (size_t)row * WID + col;
            *reinterpret_cast<float2*>(p)             = make_float2(acc[i][j][0], acc[i][j][1]);
            *reinterpret_cast<float2*>(p + 8*WID)     = make_float2(acc[i][j][2], acc[i][j][3]);
        }
    }
}

// ---------------- B-spline grid ----------------
__device__ __forceinline__ float gridpt(int j){
    const float h = 2.0f/5.0f;
    return (float)(j-3)*h - 1.0f;
}

// ---------------- expand A = [x | basis(x)] into fp16 hi/lo ----------------
__global__ void expandA_kernel(const float* __restrict__ x, int NIN){
    int idx = blockIdx.x*blockDim.x + threadIdx.x;
    int total = BATCH*NIN;
    if (idx >= total) return;
    int b = idx / NIN;
    int i = idx - b*NIN;
    float xv = x[idx];

    float bas[11];
    #pragma unroll
    for (int c=0;c<11;c++)
        bas[c] = (xv >= gridpt(c) && xv < gridpt(c+1)) ? 1.0f : 0.0f;
    #pragma unroll
    for (int p=1;p<=3;p++){
        #pragma unroll
        for (int c=0;c<=10-p;c++){
            float t1 = (xv - gridpt(c)) / (gridpt(c+p)   - gridpt(c)   + 1e-8f) * bas[c];
            float t2 = (gridpt(c+p+1) - xv) / (gridpt(c+p+1) - gridpt(c+1) + 1e-8f) * bas[c+1];
            bas[c] = t1 + t2;
        }
    }
    int K = 9*NIN;
    size_t rb = (size_t)b*K;
    __half hh = __float2half_rn(xv);
    g_Ahi[rb + i] = hh;
    g_Alo[rb + i] = __float2half_rn(xv - __half2float(hh));
    size_t off = rb + NIN + (size_t)i*8;
    __half hi8[8], lo8[8];
    #pragma unroll
    for (int c=0;c<8;c++){
        float v = bas[c];
        __half vh = __float2half_rn(v);
        hi8[c] = vh;
        lo8[c] = __float2half_rn(v - __half2float(vh));
    }
    *reinterpret_cast<uint4*>(&g_Ahi[off]) = *reinterpret_cast<uint4*>(hi8);
    *reinterpret_cast<uint4*>(&g_Alo[off]) = *reinterpret_cast<uint4*>(lo8);
}

// ---------------- expand W = [base_w | round(spline_w*32)/32] ----------------
__global__ void expandW_kernel(const float* __restrict__ bw, const float* __restrict__ sw, int NIN){
    int idx = blockIdx.x*blockDim.x + threadIdx.x;
    int K = 9*NIN;
    int total = WID*K;
    if (idx >= total) return;
    int o = idx / K;
    int k = idx - o*K;
    if (k < NIN){
        float w = bw[(size_t)o*NIN + k];
        __half wh = __float2half_rn(w);
        g_Whi[idx] = wh;
        g_Wlo[(size_t)o*NIN + k] = __float2half_rn(w - __half2float(wh));
    } else {
        float w = sw[(size_t)o*NIN*8 + (k - NIN)];
        w = rintf(w * 32.0f) * 0.03125f;      // exact in fp16 -> no lo part
        g_Whi[idx] = __float2half_rn(w);
    }
}

// ---------------- huxley_rd + trig_unfolding (1 block per row) ----------------
#define FN 1024
#define HT 256

__global__ void __launch_bounds__(HT) huxley_kernel(
    const float* __restrict__ X,
    const float* __restrict__ sgate,
    const float* __restrict__ dk,
    const float* __restrict__ a_p,
    const float* __restrict__ gamma_p,
    const float* __restrict__ tau_p,
    const float* __restrict__ vel_p,
    const float* __restrict__ gcve,
    const float* __restrict__ chir,
    float* __restrict__ out)
{
    __shared__ float2 Z[FN];
    __shared__ float2 TW[FN/2];
    __shared__ float  mg[FN/2 + 1];
    __shared__ float  red[HT];

    const int row = blockIdx.x;
    const int t = threadIdx.x;
    const float PI = 3.14159265358979323846f;

    for (int i=t;i<FN/2;i+=HT){
        float s,c;
        sincosf(-2.0f*PI*(float)i/(float)FN, &s, &c);
        TW[i] = make_float2(c, s);
    }
    for (int i=t;i<FN;i+=HT){
        unsigned r = __brev((unsigned)i) >> 22;
        Z[r] = make_float2(X[(size_t)row*FN + i], 0.0f);
    }
    __syncthreads();

    for (int s=0;s<10;s++){
        int half = 1<<s;
        for (int j=t;j<FN/2;j+=HT){
            int pos = j & (half-1);
            int i0 = ((j >> s) << (s+1)) + pos;
            int i1 = i0 + half;
            float2 w = TW[pos << (9-s)];
            float2 a = Z[i0], b = Z[i1];
            float2 wb = make_float2(w.x*b.x - w.y*b.y, w.x*b.y + w.y*b.x);
            Z[i0] = make_float2(a.x+wb.x, a.y+wb.y);
            Z[i1] = make_float2(a.x-wb.x, a.y-wb.y);
        }
        __syncthreads();
    }

    float v = vel_p[0];
    for (int k=t;k<=FN/2;k+=HT){
        float2 F = Z[k];
        float g = 1.0f/(1.0f + expf(-sgate[k]));
        float og = 1.0f - g;
        float ps, pc;
        sincosf(-2.0f*PI*(float)k*v/(float)FN, &ps, &pc);
        float2 nef = make_float2(F.x*og, F.y*og);
        float2 S = make_float2(nef.x*pc - nef.y*ps, nef.x*ps + nef.y*pc);
        float2 E = make_float2(F.x*g, F.y*g);
        if (k==0 || k==FN/2){
            mg[k] = fabsf(S.x);
            Z[k] = make_float2(E.x, S.x);
        } else {
            mg[k] = sqrtf(nef.x*nef.x + nef.y*nef.y);
            Z[k]    = make_float2(E.x - S.y, E.y + S.x);
            Z[FN-k] = make_float2(E.x + S.y, S.x - E.y);
        }
    }
    __syncthreads();

    float ls=0.0f, lmin=3.4e38f;
    for (int k=t;k<=FN/2;k+=HT){ ls += mg[k]; lmin = fminf(lmin, mg[k]); }
    red[t]=ls; __syncthreads();
    for (int o=HT/2;o>0;o>>=1){ if(t<o) red[t]+=red[t+o]; __syncthreads(); }
    float mean = red[0] / 513.0f; __syncthreads();
    red[t]=lmin; __syncthreads();
    for (int o=HT/2;o>0;o>>=1){ if(t<o) red[t]=fminf(red[t],red[t+o]); __syncthreads(); }
    float lam_min = red[0]; __syncthreads();
    float lv=0.0f;
    for (int k=t;k<=FN/2;k+=HT){ float d = mg[k]-mean; lv += d*d; }
    red[t]=lv; __syncthreads();
    for (int o=HT/2;o>0;o>>=1){ if(t<o) red[t]+=red[t+o]; __syncthreads(); }
    float var = red[0] / 512.0f; __syncthreads();

    for (int i=t;i<FN;i+=HT){
        unsigned r = __brev((unsigned)i) >> 22;
        if (i < (int)r){ float2 tmp = Z[i]; Z[i]=Z[r]; Z[r]=tmp; }
    }
    __syncthreads();
    for (int s=0;s<10;s++){
        int half = 1<<s;
        for (int j=t;j<FN/2;j+=HT){
            int pos = j & (half-1);
            int i0 = ((j >> s) << (s+1)) + pos;
            int i1 = i0 + half;
            float2 w = TW[pos << (9-s)];
            w.y = -w.y;
            float2 a = Z[i0], b = Z[i1];
            float2 wb = make_float2(w.x*b.x - w.y*b.y, w.x*b.y + w.y*b.x);
            Z[i0] = make_float2(a.x+wb.x, a.y+wb.y);
            Z[i1] = make_float2(a.x-wb.x, a.y-wb.y);
        }
        __syncthreads();
    }

    const float scale = 1.0f/(float)FN;
    float lt = 0.0f;
    for (int n=t;n<FN;n+=HT){ float hh = Z[n].y*scale; lt += hh*hh; }
    red[t]=lt; __syncthreads();
    for (int o=HT/2;o>0;o>>=1){ if(t<o) red[t]+=red[t+o]; __syncthreads(); }
    float tr_c = red[0]; __syncthreads();

    float tau = tau_p[0], gam = gamma_p[0], a = a_p[0];
    float k0 = dk[0], k1 = dk[1], k2 = dk[2];
    float gp = gcve[row];
    float ach = fabsf(chir[row]);

    float det = var + 1e-6f;
    float sq = sqrtf(det);
    float denom = 2.0f*(sq*sq*sq) + 1e-8f;
    float cos3 = (3.0f*gp - tr_c/tau) / denom;
    cos3 = fminf(0.999f, fmaxf(-0.999f, cos3));
    float phi = acosf(cos3) / 3.0f;
    float amp = 2.0f*sqrtf(lam_min/3.0f + 1e-8f);
    float c0 = amp * cosf(phi);
    float c1 = amp * cosf(phi + 2.0f*PI/3.0f) * expf(-ach);
    float c2 = amp * cosf(phi + 4.0f*PI/3.0f) * expf(-2.0f*ach);
    float e0=fabsf(c0), e1=fabsf(c1), e2=fabsf(c2);
    float cb = c0; float eb = e0;
    if (e1 > eb){ cb=c1; eb=e1; }
    if (e2 > eb){ cb=c2; }

    for (int n=t;n<FN;n+=HT){
        float e  = Z[n].x*scale;
        float em = (n>0)      ? Z[n-1].x*scale : 0.0f;
        float ep = (n<FN-1)   ? Z[n+1].x*scale : 0.0f;
        float reac = e*(e-a)*(1.0f-e);
        float dif  = k0*em + k1*e + k2*ep;
        float enx  = e + 0.1f*(reac + gam*dif);
        float hh   = Z[n].y*scale;
        float s    = enx + cb*hh;
        float sg   = 1.0f/(1.0f+expf(-s));
        out[(size_t)row*FN + n] = sg*s;
    }
}

// ---------------- launcher ----------------
extern "C" void kernel_launch(void* const* d_in, const int* in_sizes, int n_in,
                              void* d_out, int out_size) {
    const float* c   = (const float*)d_in[0];
    const float* bw0 = (const float*)d_in[1];
    const float* sw0 = (const float*)d_in[2];
    const float* bw1 = (const float*)d_in[3];
    const float* sw1 = (const float*)d_in[4];
    const float* bw2 = (const float*)d_in[5];
    const float* sw2 = (const float*)d_in[6];
    const float* sg  = (const float*)d_in[7];
    const float* dk  = (const float*)d_in[8];
    const float* ap  = (const float*)d_in[9];
    const float* gm  = (const float*)d_in[10];
    const float* td  = (const float*)d_in[11];
    const float* sv  = (const float*)d_in[12];
    const float* gp  = (const float*)d_in[13];
    const float* ch  = (const float*)d_in[14];

    void *pAhi, *pAlo, *pWhi, *pWlo;
    float *X0, *X1;
    cudaGetSymbolAddress(&pAhi, g_Ahi);
    cudaGetSymbolAddress(&pAlo, g_Alo);
    cudaGetSymbolAddress(&pWhi, g_Whi);
    cudaGetSymbolAddress(&pWlo, g_Wlo);
    cudaGetSymbolAddress((void**)&X0, g_X0);
    cudaGetSymbolAddress((void**)&X1, g_X1);

    cudaFuncSetAttribute(hmma_gemm, cudaFuncAttributeMaxDynamicSharedMemorySize, SMEM_BYTES);

    dim3 gblk(WID/128, BATCH/128);   // (8, 32)

    struct LayerCfg { const float* bw; const float* sw; const float* in; float* out; int nin; };
    LayerCfg L[3] = {
        { bw0, sw0, c,  X0, 512  },
        { bw1, sw1, X0, X1, 1024 },
        { bw2, sw2, X1, X0, 1024 },
    };

    for (int l = 0; l < 3; l++) {
        int NIN = L[l].nin;
        int K   = 9 * NIN;
        int Kb  = NIN;

        expandW_kernel<<<(WID*K + 255)/256, 256>>>(L[l].bw, L[l].sw, NIN);
        expandA_kernel<<<(BATCH*NIN + 255)/256, 256>>>(L[l].in, NIN);

        hmma_gemm<<<gblk, 256, SMEM_BYTES>>>(
            (const __half*)pAhi, (const __half*)pAlo,
            (const __half*)pWhi, (const __half*)pWlo,
            L[l].out, K, Kb);
    }

    huxley_kernel<<<BATCH, HT>>>(X0, sg, dk, ap, gm, td, sv, gp, ch, (float*)d_out);
}